// round 3
// baseline (speedup 1.0000x reference)
#include <cuda_runtime.h>

#define NNODES 40000
#define NEDGES 640000
#define TE     (NEDGES + NNODES)
#define CH     128
#define BN_EPS 1e-5f
#define NEG    0.2f
#define SCAN_BLOCKS ((NNODES + 255) / 256)

// ---------------- scratch (device globals: no allocation allowed) ----------
__device__ __align__(16) float g_xl[NNODES * CH];
__device__ __align__(16) float g_xr[NNODES * CH];
__device__ __align__(16) float g_h [NNODES * CH];
__device__ __align__(16) int   g_deg[NNODES];
__device__ __align__(16) int   g_rowstart[NNODES + 4];
__device__ __align__(16) int   g_cursor[NNODES];
__device__             int     g_csr[TE];
__device__             int     g_partial[SCAN_BLOCKS + 4];

// ---------------- CSR build --------------------------------------------------
__global__ void k_init_deg() {
    int i = blockIdx.x * blockDim.x + threadIdx.x;
    if (i < NNODES) g_deg[i] = 1;  // self loop
}

__global__ void k_hist(const int* __restrict__ dst) {
    int i = blockIdx.x * blockDim.x + threadIdx.x;
    if (i < NEDGES) atomicAdd(&g_deg[dst[i]], 1);
}

// multi-block scan: (1) per-block reduce, (2) scan partials, (3) scan + offset
__global__ void k_scan1() {
    __shared__ int sm[256];
    int i = blockIdx.x * 256 + threadIdx.x;
    int v = (i < NNODES) ? g_deg[i] : 0;
    sm[threadIdx.x] = v;
    __syncthreads();
    #pragma unroll
    for (int off = 128; off; off >>= 1) {
        if (threadIdx.x < off) sm[threadIdx.x] += sm[threadIdx.x + off];
        __syncthreads();
    }
    if (threadIdx.x == 0) g_partial[blockIdx.x] = sm[0];
}

__global__ void k_scan2() {
    __shared__ int sm[256];
    int t = threadIdx.x;
    int v = (t < SCAN_BLOCKS) ? g_partial[t] : 0;
    sm[t] = v;
    __syncthreads();
    int val = v;
    #pragma unroll
    for (int off = 1; off < 256; off <<= 1) {
        int u = (t >= off) ? sm[t - off] : 0;
        __syncthreads();
        val += u;
        sm[t] = val;
        __syncthreads();
    }
    if (t < SCAN_BLOCKS) g_partial[t] = val - v;  // exclusive
}

__global__ void k_scan3() {
    __shared__ int sm[256];
    int t = threadIdx.x;
    int i = blockIdx.x * 256 + t;
    int v = (i < NNODES) ? g_deg[i] : 0;
    sm[t] = v;
    __syncthreads();
    int val = v;
    #pragma unroll
    for (int off = 1; off < 256; off <<= 1) {
        int u = (t >= off) ? sm[t - off] : 0;
        __syncthreads();
        val += u;
        sm[t] = val;
        __syncthreads();
    }
    int excl = g_partial[blockIdx.x] + val - v;
    if (i < NNODES) {
        g_rowstart[i] = excl;
        g_cursor[i]   = excl;
    }
    if (i == NNODES - 1) g_rowstart[NNODES] = excl + v;
}

__global__ void k_scatter(const int* __restrict__ ei) {
    int i = blockIdx.x * blockDim.x + threadIdx.x;
    if (i < NEDGES) {
        int s = ei[i];
        int d = ei[NEDGES + i];
        int pos = atomicAdd(&g_cursor[d], 1);
        g_csr[pos] = s;
    } else if (i < TE) {
        int node = i - NEDGES;
        int pos = atomicAdd(&g_cursor[node], 1);
        g_csr[pos] = node;
    }
}

// ---------------- TF32 tensor-core GEMM --------------------------------------
#define SA_STRIDE 132
#define SB_STRIDE 136
#define SMEM_UINTS (128 * SA_STRIDE + 2 * 128 * SB_STRIDE)
#define SMEM_BYTES (SMEM_UINTS * 4)

__device__ __forceinline__ unsigned f2tf(float x) {
    unsigned r;
    asm("cvt.rna.tf32.f32 %0, %1;" : "=r"(r) : "f"(x));
    return r;
}

__device__ __forceinline__ void mma_tf32(float* c, const unsigned* a,
                                         unsigned b0, unsigned b1) {
    asm volatile(
        "mma.sync.aligned.m16n8k8.row.col.f32.tf32.tf32.f32 "
        "{%0,%1,%2,%3}, {%4,%5,%6,%7}, {%8,%9}, {%0,%1,%2,%3};"
        : "+f"(c[0]), "+f"(c[1]), "+f"(c[2]), "+f"(c[3])
        : "r"(a[0]), "r"(a[1]), "r"(a[2]), "r"(a[3]), "r"(b0), "r"(b1));
}

__global__ __launch_bounds__(256) void k_mm_tc(
    const float* __restrict__ Aext, int asel,
    const float* __restrict__ B1, const float* __restrict__ bias1,
    const float* __restrict__ B2, const float* __restrict__ bias2,
    int dual, int relu, int M)
{
    extern __shared__ unsigned smem[];
    unsigned* sA  = smem;
    unsigned* sB0 = sA + 128 * SA_STRIDE;
    unsigned* sB1 = sB0 + 128 * SB_STRIDE;

    const float* A = asel ? (const float*)g_h : Aext;
    const int tid = threadIdx.x;
    const int wid = tid >> 5, lane = tid & 31;
    const int q = lane & 3, g = lane >> 2;
    const int row0 = blockIdx.x * 128;

    #pragma unroll
    for (int l = 0; l < 16; l++) {
        int i = tid + l * 256;
        int r = i >> 5, c = (i & 31) << 2;
        float4 v = make_float4(0.f, 0.f, 0.f, 0.f);
        int gr = row0 + r;
        if (gr < M) v = *(const float4*)&A[gr * 128 + c];
        uint4 t;
        t.x = f2tf(v.x); t.y = f2tf(v.y); t.z = f2tf(v.z); t.w = f2tf(v.w);
        *(uint4*)&sA[r * SA_STRIDE + c] = t;
    }
    #pragma unroll
    for (int l = 0; l < 16; l++) {
        int i = tid + l * 256;
        int r = i >> 5, c = (i & 31) << 2;
        float4 v = *(const float4*)&B1[r * 128 + c];
        uint4 t;
        t.x = f2tf(v.x); t.y = f2tf(v.y); t.z = f2tf(v.z); t.w = f2tf(v.w);
        *(uint4*)&sB0[r * SB_STRIDE + c] = t;
    }
    if (dual) {
        #pragma unroll
        for (int l = 0; l < 16; l++) {
            int i = tid + l * 256;
            int r = i >> 5, c = (i & 31) << 2;
            float4 v = *(const float4*)&B2[r * 128 + c];
            uint4 t;
            t.x = f2tf(v.x); t.y = f2tf(v.y); t.z = f2tf(v.z); t.w = f2tf(v.w);
            *(uint4*)&sB1[r * SB_STRIDE + c] = t;
        }
    }
    __syncthreads();

    int m_tiles, wr, colbase;
    const unsigned* sB;
    const float* bias;
    float* C;
    if (dual) {
        int gm = wid >> 2;
        wr = ((wid >> 1) & 1) * 64;
        colbase = (wid & 1) * 64;
        m_tiles = 4;
        sB = gm ? sB1 : sB0;
        bias = gm ? bias2 : bias1;
        C = gm ? g_xr : g_xl;
    } else {
        wr = (wid >> 1) * 32;
        colbase = (wid & 1) * 64;
        m_tiles = 2;
        sB = sB0;
        bias = bias1;
        C = g_xl;
    }

    float acc[4][8][4];
    #pragma unroll
    for (int mt = 0; mt < 4; mt++)
        #pragma unroll
        for (int nt = 0; nt < 8; nt++)
            #pragma unroll
            for (int j = 0; j < 4; j++) acc[mt][nt][j] = 0.f;

    for (int ks = 0; ks < 16; ks++) {
        int k0 = ks * 8;
        unsigned a[4][4];
        #pragma unroll
        for (int mt = 0; mt < 4; mt++)
            if (mt < m_tiles) {
                int rb = wr + mt * 16;
                a[mt][0] = sA[(rb + g) * SA_STRIDE + k0 + q];
                a[mt][1] = sA[(rb + 8 + g) * SA_STRIDE + k0 + q];
                a[mt][2] = sA[(rb + g) * SA_STRIDE + k0 + q + 4];
                a[mt][3] = sA[(rb + 8 + g) * SA_STRIDE + k0 + q + 4];
            }
        #pragma unroll
        for (int nt = 0; nt < 8; nt++) {
            int cb = colbase + nt * 8 + g;
            unsigned b0 = sB[(k0 + q) * SB_STRIDE + cb];
            unsigned b1 = sB[(k0 + q + 4) * SB_STRIDE + cb];
            #pragma unroll
            for (int mt = 0; mt < 4; mt++)
                if (mt < m_tiles) mma_tf32(acc[mt][nt], a[mt], b0, b1);
        }
    }

    #pragma unroll
    for (int nt = 0; nt < 8; nt++) {
        int col = colbase + nt * 8 + q * 2;
        float2 bb = *(const float2*)&bias[col];
        #pragma unroll
        for (int mt = 0; mt < 4; mt++)
            if (mt < m_tiles) {
                int r0 = row0 + wr + mt * 16 + g;
                float v0 = acc[mt][nt][0] + bb.x;
                float v1 = acc[mt][nt][1] + bb.y;
                float v2 = acc[mt][nt][2] + bb.x;
                float v3 = acc[mt][nt][3] + bb.y;
                if (relu) {
                    v0 = fmaxf(v0, 0.f); v1 = fmaxf(v1, 0.f);
                    v2 = fmaxf(v2, 0.f); v3 = fmaxf(v3, 0.f);
                }
                if (r0 < M)
                    *(float2*)&C[r0 * 128 + col] = make_float2(v0, v1);
                if (r0 + 8 < M)
                    *(float2*)&C[(r0 + 8) * 128 + col] = make_float2(v2, v3);
            }
    }
}

// ---------------- GAT: warp/dst, chunk-16 unrolled, transpose-reduce ---------
__global__ __launch_bounds__(128) void k_gat(
    const float* __restrict__ att, const float* __restrict__ bias,
    const float* __restrict__ gg, const float* __restrict__ be,
    const float* __restrict__ rm, const float* __restrict__ rv)
{
    const unsigned FULL = 0xffffffffu;
    int w = blockIdx.x * 4 + (threadIdx.x >> 5);
    int lane = threadIdx.x & 31;
    if (w >= NNODES) return;
    int c0 = lane * 4;
    int e = lane & 15;

    float4 xr4 = *(const float4*)&g_xr[w * CH + c0];
    float4 at4 = *(const float4*)&att[c0];

    int rs = g_rowstart[w];
    int re = g_rowstart[w + 1];

    const float NINF = __int_as_float(0xff800000);
    float gm = NINF, gs = 0.f;
    float ga0 = 0.f, ga1 = 0.f, ga2 = 0.f, ga3 = 0.f;

    for (int base = rs; base < re; base += 16) {
        int cnt = min(16, re - base);
        int lidx = base + e;
        int msrc = (lidx < re) ? g_csr[lidx] : 0;

        float p[16];
        float4 xl[16];
        #pragma unroll
        for (int t = 0; t < 16; t++) {
            if (t < cnt) {
                int sn = __shfl_sync(FULL, msrc, t);
                xl[t] = *(const float4*)&g_xl[sn * CH + c0];
                float a0 = xl[t].x + xr4.x;
                float a1 = xl[t].y + xr4.y;
                float a2 = xl[t].z + xr4.z;
                float a3 = xl[t].w + xr4.w;
                a0 = fmaf(NEG, fminf(a0, 0.f), fmaxf(a0, 0.f));
                a1 = fmaf(NEG, fminf(a1, 0.f), fmaxf(a1, 0.f));
                a2 = fmaf(NEG, fminf(a2, 0.f), fmaxf(a2, 0.f));
                a3 = fmaf(NEG, fminf(a3, 0.f), fmaxf(a3, 0.f));
                p[t] = a0 * at4.x + a1 * at4.y + a2 * at4.z + a3 * at4.w;
            } else {
                p[t] = 0.f;
                xl[t] = make_float4(0.f, 0.f, 0.f, 0.f);
            }
        }

        // fold upper 16 lanes onto lower image
        #pragma unroll
        for (int t = 0; t < 16; t++)
            p[t] += __shfl_xor_sync(FULL, p[t], 16);
        // halving transpose-reduce: lane (l&15)=e ends holding logit_e
        #pragma unroll
        for (int off = 8; off > 0; off >>= 1) {
            #pragma unroll
            for (int t = 0; t < off; t++) {
                float mine  = (lane & off) ? p[t] : p[t + off];
                float other = __shfl_xor_sync(FULL, mine, off);
                p[t] = ((lane & off) ? p[t + off] : p[t]) + other;
            }
        }
        float logit = (e < cnt) ? p[0] : NINF;

        // chunk max (over 16-lane group)
        float m = logit;
        #pragma unroll
        for (int off = 8; off; off >>= 1)
            m = fmaxf(m, __shfl_xor_sync(FULL, m, off));

        float pe = (e < cnt) ? __expf(logit - m) : 0.f;
        float s = pe;
        #pragma unroll
        for (int off = 8; off; off >>= 1)
            s += __shfl_xor_sync(FULL, s, off);

        // chunk aggregation
        float cx = 0.f, cy = 0.f, cz = 0.f, cw = 0.f;
        #pragma unroll
        for (int t = 0; t < 16; t++) {
            if (t < cnt) {
                float pt = __shfl_sync(FULL, pe, t);
                cx = fmaf(pt, xl[t].x, cx);
                cy = fmaf(pt, xl[t].y, cy);
                cz = fmaf(pt, xl[t].z, cz);
                cw = fmaf(pt, xl[t].w, cw);
            }
        }

        // online merge of chunk into global
        float nm = fmaxf(gm, m);
        float f1 = __expf(gm - nm);
        float f2 = __expf(m - nm);
        gs  = gs  * f1 + s  * f2;
        ga0 = ga0 * f1 + cx * f2;
        ga1 = ga1 * f1 + cy * f2;
        ga2 = ga2 * f1 + cz * f2;
        ga3 = ga3 * f1 + cw * f2;
        gm = nm;
    }

    float inv = 1.f / gs;
    float4 b4  = *(const float4*)&bias[c0];
    float4 g4  = *(const float4*)&gg[c0];
    float4 be4 = *(const float4*)&be[c0];
    float4 rm4 = *(const float4*)&rm[c0];
    float4 rv4 = *(const float4*)&rv[c0];

    float4 o;
    o.x = fmaxf((ga0 * inv + b4.x - rm4.x) * (g4.x * rsqrtf(rv4.x + BN_EPS)) + be4.x, 0.f);
    o.y = fmaxf((ga1 * inv + b4.y - rm4.y) * (g4.y * rsqrtf(rv4.y + BN_EPS)) + be4.y, 0.f);
    o.z = fmaxf((ga2 * inv + b4.z - rm4.z) * (g4.z * rsqrtf(rv4.z + BN_EPS)) + be4.z, 0.f);
    o.w = fmaxf((ga3 * inv + b4.w - rm4.w) * (g4.w * rsqrtf(rv4.w + BN_EPS)) + be4.w, 0.f);
    *(float4*)&g_h[w * CH + c0] = o;
}

// ---------------- final tiny GEMM: out[M,2] = X[M,128] @ W[128,2] + b --------
__global__ void k_lin2(const float* __restrict__ W, const float* __restrict__ b,
                       float* __restrict__ out)
{
    int w = (blockIdx.x * blockDim.x + threadIdx.x) >> 5;
    int lane = threadIdx.x & 31;
    if (w >= NNODES) return;
    float4 v  = *(const float4*)&g_xl[w * CH + lane * 4];
    float4 w0 = *(const float4*)&W[lane * 8];
    float4 w1 = *(const float4*)&W[lane * 8 + 4];
    float s0 = v.x * w0.x + v.y * w0.z + v.z * w1.x + v.w * w1.z;
    float s1 = v.x * w0.y + v.y * w0.w + v.z * w1.y + v.w * w1.w;
    #pragma unroll
    for (int o = 16; o; o >>= 1) {
        s0 += __shfl_xor_sync(0xffffffffu, s0, o);
        s1 += __shfl_xor_sync(0xffffffffu, s1, o);
    }
    if (lane == 0) {
        out[w * 2 + 0] = s0 + b[0];
        out[w * 2 + 1] = s1 + b[1];
    }
}

// ---------------- launch -----------------------------------------------------
extern "C" void kernel_launch(void* const* d_in, const int* in_sizes, int n_in,
                              void* d_out, int out_size)
{
    const float* x     = (const float*)d_in[0];
    const int*   ei    = (const int*)  d_in[1];
    const float* Wl0   = (const float*)d_in[2];
    const float* bl0   = (const float*)d_in[3];
    const float* Wr0   = (const float*)d_in[4];
    const float* br0   = (const float*)d_in[5];
    const float* att0  = (const float*)d_in[6];
    const float* bias0 = (const float*)d_in[7];
    const float* g0    = (const float*)d_in[8];
    const float* be0   = (const float*)d_in[9];
    const float* rm0   = (const float*)d_in[10];
    const float* rv0   = (const float*)d_in[11];
    const float* Wl1   = (const float*)d_in[12];
    const float* bl1   = (const float*)d_in[13];
    const float* Wr1   = (const float*)d_in[14];
    const float* br1   = (const float*)d_in[15];
    const float* att1  = (const float*)d_in[16];
    const float* bias1 = (const float*)d_in[17];
    const float* g1    = (const float*)d_in[18];
    const float* be1   = (const float*)d_in[19];
    const float* rm1   = (const float*)d_in[20];
    const float* rv1   = (const float*)d_in[21];
    const float* Wlin1 = (const float*)d_in[22];
    const float* blin1 = (const float*)d_in[23];
    const float* Wlin2 = (const float*)d_in[24];
    const float* blin2 = (const float*)d_in[25];
    float* out = (float*)d_out;

    cudaFuncSetAttribute(k_mm_tc, cudaFuncAttributeMaxDynamicSharedMemorySize,
                         SMEM_BYTES);

    const int GEMM_BLOCKS = (NNODES + 127) / 128;      // 313
    const int GAT_BLOCKS  = (NNODES + 3) / 4;          // 10000 (128 thr)
    const int W32_BLOCKS  = (NNODES * 32 + 255) / 256; // warp-per-node, 256 thr

    k_init_deg<<<(NNODES + 255) / 256, 256>>>();
    k_hist<<<(NEDGES + 255) / 256, 256>>>(ei + NEDGES);
    k_mm_tc<<<GEMM_BLOCKS, 256, SMEM_BYTES>>>(x, 0, Wl0, bl0, Wr0, br0, 1, 0, NNODES);
    k_scan1<<<SCAN_BLOCKS, 256>>>();
    k_scan2<<<1, 256>>>();
    k_scan3<<<SCAN_BLOCKS, 256>>>();
    k_scatter<<<(TE + 255) / 256, 256>>>(ei);

    k_gat<<<GAT_BLOCKS, 128>>>(att0, bias0, g0, be0, rm0, rv0);

    k_mm_tc<<<GEMM_BLOCKS, 256, SMEM_BYTES>>>(nullptr, 1, Wl1, bl1, Wr1, br1, 1, 0, NNODES);
    k_gat<<<GAT_BLOCKS, 128>>>(att1, bias1, g1, be1, rm1, rv1);

    k_mm_tc<<<GEMM_BLOCKS, 256, SMEM_BYTES>>>(nullptr, 1, Wlin1, blin1, nullptr, nullptr, 0, 1, NNODES);
    k_lin2<<<W32_BLOCKS, 256>>>(Wlin2, blin2, out);
}

// round 5
// speedup vs baseline: 2.1026x; 2.1026x over previous
#include <cuda_runtime.h>

#define NNODES 40000
#define NEDGES 640000
#define TE     (NEDGES + NNODES)
#define CH     128
#define BN_EPS 1e-5f
#define NEG    0.2f
#define SCAN_BLOCKS ((NNODES + 255) / 256)

// ---------------- scratch (device globals: no allocation allowed) ----------
__device__ __align__(16) float g_xl[NNODES * CH];
__device__ __align__(16) float g_xr[NNODES * CH];
__device__ __align__(16) float g_h [NNODES * CH];
__device__ __align__(16) int   g_deg[NNODES];
__device__ __align__(16) int   g_rowstart[NNODES + 4];
__device__ __align__(16) int   g_cursor[NNODES];
__device__             int     g_csr[TE];
__device__             int     g_partial[SCAN_BLOCKS + 4];

// ---------------- CSR build --------------------------------------------------
__global__ void k_init_deg() {
    int i = blockIdx.x * blockDim.x + threadIdx.x;
    if (i < NNODES) g_deg[i] = 1;  // self loop
}

__global__ void k_hist(const int* __restrict__ dst) {
    int i = blockIdx.x * blockDim.x + threadIdx.x;
    if (i < NEDGES) atomicAdd(&g_deg[dst[i]], 1);
}

__global__ void k_scan1() {
    __shared__ int sm[256];
    int i = blockIdx.x * 256 + threadIdx.x;
    int v = (i < NNODES) ? g_deg[i] : 0;
    sm[threadIdx.x] = v;
    __syncthreads();
    #pragma unroll
    for (int off = 128; off; off >>= 1) {
        if (threadIdx.x < off) sm[threadIdx.x] += sm[threadIdx.x + off];
        __syncthreads();
    }
    if (threadIdx.x == 0) g_partial[blockIdx.x] = sm[0];
}

__global__ void k_scan2() {
    __shared__ int sm[256];
    int t = threadIdx.x;
    int v = (t < SCAN_BLOCKS) ? g_partial[t] : 0;
    sm[t] = v;
    __syncthreads();
    int val = v;
    #pragma unroll
    for (int off = 1; off < 256; off <<= 1) {
        int u = (t >= off) ? sm[t - off] : 0;
        __syncthreads();
        val += u;
        sm[t] = val;
        __syncthreads();
    }
    if (t < SCAN_BLOCKS) g_partial[t] = val - v;  // exclusive
}

__global__ void k_scan3() {
    __shared__ int sm[256];
    int t = threadIdx.x;
    int i = blockIdx.x * 256 + t;
    int v = (i < NNODES) ? g_deg[i] : 0;
    sm[t] = v;
    __syncthreads();
    int val = v;
    #pragma unroll
    for (int off = 1; off < 256; off <<= 1) {
        int u = (t >= off) ? sm[t - off] : 0;
        __syncthreads();
        val += u;
        sm[t] = val;
        __syncthreads();
    }
    int excl = g_partial[blockIdx.x] + val - v;
    if (i < NNODES) {
        g_rowstart[i] = excl;
        g_cursor[i]   = excl;
    }
    if (i == NNODES - 1) g_rowstart[NNODES] = excl + v;
}

__global__ void k_scatter(const int* __restrict__ ei) {
    int i = blockIdx.x * blockDim.x + threadIdx.x;
    if (i < NEDGES) {
        int s = ei[i];
        int d = ei[NEDGES + i];
        int pos = atomicAdd(&g_cursor[d], 1);
        g_csr[pos] = s;
    } else if (i < TE) {
        int node = i - NEDGES;
        int pos = atomicAdd(&g_cursor[node], 1);
        g_csr[pos] = node;
    }
}

// ---------------- TF32 tensor-core GEMM, occupancy-tuned --------------------
// Block tile 64x128 (M=40000=625*64 exact). 8 warps, warp tile 16x64.
// blockIdx.y selects output: y==0 -> B1 -> g_xl ; y==1 -> B2 -> g_xr.
#define SA_STRIDE 132
#define SB_STRIDE 136
#define MM_SMEM_UINTS (64 * SA_STRIDE + 128 * SB_STRIDE)
#define MM_SMEM_BYTES (MM_SMEM_UINTS * 4)

__device__ __forceinline__ unsigned f2tf(float x) {
    unsigned r;
    asm("cvt.rna.tf32.f32 %0, %1;" : "=r"(r) : "f"(x));
    return r;
}

__device__ __forceinline__ void mma_tf32(float* c, const unsigned* a,
                                         unsigned b0, unsigned b1) {
    asm volatile(
        "mma.sync.aligned.m16n8k8.row.col.f32.tf32.tf32.f32 "
        "{%0,%1,%2,%3}, {%4,%5,%6,%7}, {%8,%9}, {%0,%1,%2,%3};"
        : "+f"(c[0]), "+f"(c[1]), "+f"(c[2]), "+f"(c[3])
        : "r"(a[0]), "r"(a[1]), "r"(a[2]), "r"(a[3]), "r"(b0), "r"(b1));
}

__global__ __launch_bounds__(256, 2) void k_mm_tc(
    const float* __restrict__ Aext, int asel,
    const float* __restrict__ B1, const float* __restrict__ bias1,
    const float* __restrict__ B2, const float* __restrict__ bias2,
    int relu)
{
    extern __shared__ unsigned smem[];
    unsigned* sA = smem;                       // [64][132]
    unsigned* sB = sA + 64 * SA_STRIDE;        // [128][136]

    const float* A = asel ? (const float*)g_h : Aext;
    const float* B    = blockIdx.y ? B2    : B1;
    const float* bias = blockIdx.y ? bias2 : bias1;
    float*       C    = blockIdx.y ? g_xr  : g_xl;

    const int tid = threadIdx.x;
    const int wid = tid >> 5, lane = tid & 31;
    const int q = lane & 3, g = lane >> 2;
    const int row0 = blockIdx.x * 64;
    const int mrow = (wid >> 1) * 16;          // 0,16,32,48
    const int colb = (wid & 1) * 64;           // 0 or 64

    // stage A (64x128, tf32): 2048 float4s -> 8 per thread
    #pragma unroll
    for (int l = 0; l < 8; l++) {
        int i = tid + l * 256;                 // 0..2047
        int r = i >> 5, c = (i & 31) << 2;     // r 0..63, c 0..124
        float4 v = *(const float4*)&A[(row0 + r) * 128 + c];
        uint4 t;
        t.x = f2tf(v.x); t.y = f2tf(v.y); t.z = f2tf(v.z); t.w = f2tf(v.w);
        *(uint4*)&sA[r * SA_STRIDE + c] = t;
    }
    // stage B (128x128, tf32): 4096 float4s -> 16 per thread
    #pragma unroll
    for (int l = 0; l < 16; l++) {
        int i = tid + l * 256;                 // 0..4095
        int r = i >> 5, c = (i & 31) << 2;     // r 0..127, c 0..124
        float4 v = *(const float4*)&B[r * 128 + c];
        uint4 t;
        t.x = f2tf(v.x); t.y = f2tf(v.y); t.z = f2tf(v.z); t.w = f2tf(v.w);
        *(uint4*)&sB[r * SB_STRIDE + c] = t;
    }
    __syncthreads();

    float acc[8][4];
    #pragma unroll
    for (int nt = 0; nt < 8; nt++)
        #pragma unroll
        for (int j = 0; j < 4; j++) acc[nt][j] = 0.f;

    #pragma unroll
    for (int ks = 0; ks < 16; ks++) {
        int k0 = ks * 8;
        unsigned a[4];
        a[0] = sA[(mrow + g) * SA_STRIDE + k0 + q];
        a[1] = sA[(mrow + 8 + g) * SA_STRIDE + k0 + q];
        a[2] = sA[(mrow + g) * SA_STRIDE + k0 + q + 4];
        a[3] = sA[(mrow + 8 + g) * SA_STRIDE + k0 + q + 4];
        #pragma unroll
        for (int nt = 0; nt < 8; nt++) {
            int cb = colb + nt * 8 + g;
            unsigned b0 = sB[(k0 + q) * SB_STRIDE + cb];
            unsigned b1 = sB[(k0 + q + 4) * SB_STRIDE + cb];
            mma_tf32(acc[nt], a, b0, b1);
        }
    }

    #pragma unroll
    for (int nt = 0; nt < 8; nt++) {
        int col = colb + nt * 8 + q * 2;
        float2 bb = *(const float2*)&bias[col];
        int r0 = row0 + mrow + g;
        float v0 = acc[nt][0] + bb.x;
        float v1 = acc[nt][1] + bb.y;
        float v2 = acc[nt][2] + bb.x;
        float v3 = acc[nt][3] + bb.y;
        if (relu) {
            v0 = fmaxf(v0, 0.f); v1 = fmaxf(v1, 0.f);
            v2 = fmaxf(v2, 0.f); v3 = fmaxf(v3, 0.f);
        }
        *(float2*)&C[r0 * 128 + col]       = make_float2(v0, v1);
        *(float2*)&C[(r0 + 8) * 128 + col] = make_float2(v2, v3);
    }
}

// ---------------- GAT edge aggregation: one warp per destination node --------
__global__ __launch_bounds__(256) void k_gat(
    const float* __restrict__ att, const float* __restrict__ bias,
    const float* __restrict__ g, const float* __restrict__ be,
    const float* __restrict__ rm, const float* __restrict__ rv)
{
    int w = (blockIdx.x * blockDim.x + threadIdx.x) >> 5;
    int lane = threadIdx.x & 31;
    if (w >= NNODES) return;
    int c0 = lane * 4;

    float4 xr4 = *(const float4*)&g_xr[w * CH + c0];
    float4 at4 = *(const float4*)&att[c0];

    int rs = g_rowstart[w];
    int re = g_rowstart[w + 1];

    float mx = __int_as_float(0xff800000);
    float ss = 0.f;
    float ax = 0.f, ay = 0.f, az = 0.f, aw = 0.f;

    for (int base = rs; base < re; base += 32) {
        int myidx = base + lane;
        int msrc = (myidx < re) ? g_csr[myidx] : 0;
        int cnt = min(32, re - base);
        for (int t = 0; t < cnt; t++) {
            int sn = __shfl_sync(0xffffffffu, msrc, t);
            float4 xl4 = *(const float4*)&g_xl[sn * CH + c0];
            float tx_ = xl4.x + xr4.x;
            float ty_ = xl4.y + xr4.y;
            float tz_ = xl4.z + xr4.z;
            float tw_ = xl4.w + xr4.w;
            tx_ = fmaxf(tx_, 0.f) + NEG * fminf(tx_, 0.f);
            ty_ = fmaxf(ty_, 0.f) + NEG * fminf(ty_, 0.f);
            tz_ = fmaxf(tz_, 0.f) + NEG * fminf(tz_, 0.f);
            tw_ = fmaxf(tw_, 0.f) + NEG * fminf(tw_, 0.f);
            float part = tx_ * at4.x + ty_ * at4.y + tz_ * at4.z + tw_ * at4.w;
            #pragma unroll
            for (int o = 16; o; o >>= 1)
                part += __shfl_xor_sync(0xffffffffu, part, o);
            float nm = fmaxf(mx, part);
            float c = __expf(mx - nm);
            float p = __expf(part - nm);
            ss = ss * c + p;
            ax = fmaf(ax, c, p * xl4.x);
            ay = fmaf(ay, c, p * xl4.y);
            az = fmaf(az, c, p * xl4.z);
            aw = fmaf(aw, c, p * xl4.w);
            mx = nm;
        }
    }

    float inv = 1.f / ss;
    float4 b4  = *(const float4*)&bias[c0];
    float4 g4  = *(const float4*)&g[c0];
    float4 be4 = *(const float4*)&be[c0];
    float4 rm4 = *(const float4*)&rm[c0];
    float4 rv4 = *(const float4*)&rv[c0];

    float4 o;
    o.x = fmaxf((ax * inv + b4.x - rm4.x) * (g4.x * rsqrtf(rv4.x + BN_EPS)) + be4.x, 0.f);
    o.y = fmaxf((ay * inv + b4.y - rm4.y) * (g4.y * rsqrtf(rv4.y + BN_EPS)) + be4.y, 0.f);
    o.z = fmaxf((az * inv + b4.z - rm4.z) * (g4.z * rsqrtf(rv4.z + BN_EPS)) + be4.z, 0.f);
    o.w = fmaxf((aw * inv + b4.w - rm4.w) * (g4.w * rsqrtf(rv4.w + BN_EPS)) + be4.w, 0.f);
    *(float4*)&g_h[w * CH + c0] = o;
}

// ---------------- final tiny GEMM: out[M,2] = X[M,128] @ W[128,2] + b --------
__global__ void k_lin2(const float* __restrict__ W, const float* __restrict__ b,
                       float* __restrict__ out)
{
    int w = (blockIdx.x * blockDim.x + threadIdx.x) >> 5;
    int lane = threadIdx.x & 31;
    if (w >= NNODES) return;
    float4 v  = *(const float4*)&g_xl[w * CH + lane * 4];
    float4 w0 = *(const float4*)&W[lane * 8];
    float4 w1 = *(const float4*)&W[lane * 8 + 4];
    float s0 = v.x * w0.x + v.y * w0.z + v.z * w1.x + v.w * w1.z;
    float s1 = v.x * w0.y + v.y * w0.w + v.z * w1.y + v.w * w1.w;
    #pragma unroll
    for (int o = 16; o; o >>= 1) {
        s0 += __shfl_xor_sync(0xffffffffu, s0, o);
        s1 += __shfl_xor_sync(0xffffffffu, s1, o);
    }
    if (lane == 0) {
        out[w * 2 + 0] = s0 + b[0];
        out[w * 2 + 1] = s1 + b[1];
    }
}

// ---------------- launch -----------------------------------------------------
extern "C" void kernel_launch(void* const* d_in, const int* in_sizes, int n_in,
                              void* d_out, int out_size)
{
    const float* x     = (const float*)d_in[0];
    const int*   ei    = (const int*)  d_in[1];
    const float* Wl0   = (const float*)d_in[2];
    const float* bl0   = (const float*)d_in[3];
    const float* Wr0   = (const float*)d_in[4];
    const float* br0   = (const float*)d_in[5];
    const float* att0  = (const float*)d_in[6];
    const float* bias0 = (const float*)d_in[7];
    const float* g0    = (const float*)d_in[8];
    const float* be0   = (const float*)d_in[9];
    const float* rm0   = (const float*)d_in[10];
    const float* rv0   = (const float*)d_in[11];
    const float* Wl1   = (const float*)d_in[12];
    const float* bl1   = (const float*)d_in[13];
    const float* Wr1   = (const float*)d_in[14];
    const float* br1   = (const float*)d_in[15];
    const float* att1  = (const float*)d_in[16];
    const float* bias1 = (const float*)d_in[17];
    const float* g1    = (const float*)d_in[18];
    const float* be1   = (const float*)d_in[19];
    const float* rm1   = (const float*)d_in[20];
    const float* rv1   = (const float*)d_in[21];
    const float* Wlin1 = (const float*)d_in[22];
    const float* blin1 = (const float*)d_in[23];
    const float* Wlin2 = (const float*)d_in[24];
    const float* blin2 = (const float*)d_in[25];
    float* out = (float*)d_out;

    cudaFuncSetAttribute(k_mm_tc, cudaFuncAttributeMaxDynamicSharedMemorySize,
                         MM_SMEM_BYTES);

    dim3 mm_dual(625, 2), mm_single(625, 1);
    const int GAT_BLOCKS = (NNODES * 32 + 255) / 256;  // warp per node

    k_init_deg<<<(NNODES + 255) / 256, 256>>>();                         // 1
    k_hist<<<(NEDGES + 255) / 256, 256>>>(ei + NEDGES);                  // 2
    k_scan1<<<SCAN_BLOCKS, 256>>>();                                     // 3
    k_mm_tc<<<mm_dual, 256, MM_SMEM_BYTES>>>(x, 0, Wl0, bl0, Wr0, br0, 0); // 4 (capture window)
    k_scan2<<<1, 256>>>();                                               // 5
    k_scan3<<<SCAN_BLOCKS, 256>>>();                                     // 6
    k_scatter<<<(TE + 255) / 256, 256>>>(ei);                            // 7

    k_gat<<<GAT_BLOCKS, 256>>>(att0, bias0, g0, be0, rm0, rv0);          // 8

    k_mm_tc<<<mm_dual, 256, MM_SMEM_BYTES>>>(nullptr, 1, Wl1, bl1, Wr1, br1, 0); // 9
    k_gat<<<GAT_BLOCKS, 256>>>(att1, bias1, g1, be1, rm1, rv1);          // 10

    k_mm_tc<<<mm_single, 256, MM_SMEM_BYTES>>>(nullptr, 1, Wlin1, blin1, nullptr, nullptr, 1); // 11
    k_lin2<<<GAT_BLOCKS, 256>>>(Wlin2, blin2, out);                      // 12
}